// round 16
// baseline (speedup 1.0000x reference)
#include <cuda_runtime.h>

// Problem constants
#define BATCH 4
#define DD 128
#define HH 128
#define WW 128
#define SLICE (HH*WW)          // 16384
#define VOL   (DD*HH*WW)       // 2097152
#define VTOT  (BATCH*VOL)      // 8388608
#define WS 11
#define RAD 5

#define C1F 1.0e-4f            // 0.01^2
#define C2F 9.0e-4f            // 0.03^2

// Separable 1-D Gaussian, window 11, sigma 1.5, normalized (compile-time).
__device__ constexpr float WL[6] = {
    0.00102838f, 0.00759876f, 0.03600077f,
    0.10936070f, 0.21300554f, 0.26601172f
};

// Packed intermediate: float4 = (mu1, mu2, E[x^2]+E[y^2], E[xy]) per voxel.
__device__ float4 g_m4[VTOT];
__device__ double g_acc;
__device__ unsigned g_cnt;

// ---------------------------------------------------------------------------
// Packed f32x2 helpers (Blackwell fma.rn.f32x2 / mul.rn.f32x2)
// ---------------------------------------------------------------------------
__device__ __forceinline__ float2 ffma2(float2 a, float2 b, float2 c) {
    float2 d;
    asm("fma.rn.f32x2 %0, %1, %2, %3;"
        : "=l"(reinterpret_cast<unsigned long long&>(d))
        : "l"(reinterpret_cast<unsigned long long&>(a)),
          "l"(reinterpret_cast<unsigned long long&>(b)),
          "l"(reinterpret_cast<unsigned long long&>(c)));
    return d;
}
__device__ __forceinline__ float2 fmul2(float2 a, float2 b) {
    float2 d;
    asm("mul.rn.f32x2 %0, %1, %2;"
        : "=l"(reinterpret_cast<unsigned long long&>(d))
        : "l"(reinterpret_cast<unsigned long long&>(a)),
          "l"(reinterpret_cast<unsigned long long&>(b)));
    return d;
}

// ---------------------------------------------------------------------------
// K1: y-marching x+y conv. 8-row SUPERSTEPS: four row-pairs published per
// __syncthreads (10 barriers total), 12-buffer smem rotation. Race-free:
// buffer b (= step k%12) is republished 3 supersteps (3 barriers) after the
// superstep that reads it. Both buffer index (4m+i)%12 and ring-slot base
// (8m+2i)%12 have period 3 in superstep m -> unroll 3 keeps all indices
// compile-time.
// Block = 128 threads = one full x row; handles a 64-row y-half.
// Grid = (yhalf=2, z=128, b=4) = 1024 blocks.
// Block (0,0,0) resets g_acc (K2 is stream-ordered after K1).
// ---------------------------------------------------------------------------
#define RWID 138   // 128 + 2*RAD

__device__ __forceinline__ float4 fetch_pair_p(
    const float* __restrict__ p1, const float* __restrict__ p2, int row)
{
    bool ok0 = (unsigned)row < HH;
    bool ok1 = (unsigned)(row + 1) < HH;
    float4 f;
    f.x = ok0 ? __ldg(p1)      : 0.f;
    f.y = ok0 ? __ldg(p2)      : 0.f;
    f.z = ok1 ? __ldg(p1 + WW) : 0.f;
    f.w = ok1 ? __ldg(p2 + WW) : 0.f;
    return f;
}

__global__ __launch_bounds__(128, 4) void conv_xy_kernel(
    const float* __restrict__ img1, const float* __restrict__ img2)
{
    __shared__ float4 sAB[12][RWID];     // [buffer = step%12][x]: (a0,b0,a1,b1)

    const int x  = threadIdx.x;          // 0..127
    const int yh = blockIdx.x;           // 0 or 1
    const int z  = blockIdx.y;
    const int b  = blockIdx.z;
    const int y0 = yh * 64;
    const size_t base = ((size_t)b * DD + z) * SLICE;

    // Reset the reduction accumulator for this launch (graph-replay safe).
    if (yh == 0 && z == 0 && b == 0 && x == 0) g_acc = 0.0;

    // Zero the x halos of all 12 buffers once (never overwritten afterwards).
    if (x < RAD) {
        #pragma unroll
        for (int u = 0; u < 12; ++u) {
            sAB[u][x]       = make_float4(0.f, 0.f, 0.f, 0.f);
            sAB[u][133 + x] = make_float4(0.f, 0.f, 0.f, 0.f);
        }
    }
    __syncthreads();

    float2 w2s[6];
    #pragma unroll
    for (int t = 0; t < 6; ++t) w2s[t] = make_float2(WL[t], WL[t]);
    #define W2(t) w2s[((t) < 6) ? (t) : (10 - (t))]

    // Ring of 12 x-convolved rows: rMU = (mu1,mu2), rCQ = (csum, c12).
    float2 rMU[12], rCQ[12];

    // Step k consumes input rows (y0+2k-5, y0+2k-4), stores output rows
    // (y0+2k-10, y0+2k-9) when k >= 5. Superstep m = steps 4m..4m+3.
    // Prologue fetches superstep 0's 4 pairs (rows y0-5..y0+2); within
    // superstep m we fetch superstep m+1's pairs (rows y0+8m+3..y0+8m+10).
    int inRow = y0 - 5;
    const float* p1 = img1 + base + (ptrdiff_t)inRow * WW + x;
    const float* p2 = img2 + base + (ptrdiff_t)inRow * WW + x;
    float4*      po = g_m4 + base + (ptrdiff_t)(y0 - 10) * WW + x;

    float4 f[4];
    #pragma unroll
    for (int i = 0; i < 4; ++i)
        f[i] = fetch_pair_p(p1 + 2 * i * WW, p2 + 2 * i * WW, inRow + 2 * i);
    p1 += 8 * WW; p2 += 8 * WW; inRow += 8;

    // Compute one step k: x-conv from rowbuf into ring slots (SB, SB+1)%12,
    // y-conv + store (rows at po+POFF, po+POFF+WW) when k >= 5.
    #define COMPUTE(k, SB, rowbuf, POFF)                                      \
    {                                                                         \
        float2 xmu0 = make_float2(0.f, 0.f), xcv0 = make_float2(0.f, 0.f);    \
        float2 xmu1 = make_float2(0.f, 0.f), xcv1 = make_float2(0.f, 0.f);    \
        float2 xp01 = make_float2(0.f, 0.f);                                  \
        _Pragma("unroll")                                                     \
        for (int t = 0; t < WS; ++t) {                                        \
            float2 wv = W2(t);                                                \
            float4 v4 = (rowbuf)[x + t];                                      \
            float2 ab0 = make_float2(v4.x, v4.y);                             \
            float2 ab1 = make_float2(v4.z, v4.w);                             \
            float2 sq0 = fmul2(ab0, ab0);                                     \
            float2 sq1 = fmul2(ab1, ab1);                                     \
            float2 pp  = make_float2(v4.x * v4.y, v4.z * v4.w);               \
            xmu0 = ffma2(wv, ab0, xmu0);                                      \
            xcv0 = ffma2(wv, sq0, xcv0);                                      \
            xmu1 = ffma2(wv, ab1, xmu1);                                      \
            xcv1 = ffma2(wv, sq1, xcv1);                                      \
            xp01 = ffma2(wv, pp, xp01);                                       \
        }                                                                     \
        rMU[(SB) % 12]       = xmu0;                                          \
        rCQ[(SB) % 12]       = make_float2(xcv0.x + xcv0.y, xp01.x);          \
        rMU[((SB) + 1) % 12] = xmu1;                                          \
        rCQ[((SB) + 1) % 12] = make_float2(xcv1.x + xcv1.y, xp01.y);          \
        if ((k) >= 5) {                                                       \
            float2 amu0 = make_float2(0.f, 0.f), acq0 = make_float2(0.f, 0.f);\
            float2 amu1 = make_float2(0.f, 0.f), acq1 = make_float2(0.f, 0.f);\
            _Pragma("unroll")                                                 \
            for (int t = 0; t < WS; ++t) {                                    \
                float2 wv = W2(t);                                            \
                const int s0 = ((SB) + t + 2) % 12;                           \
                const int s1 = ((SB) + t + 3) % 12;                           \
                amu0 = ffma2(wv, rMU[s0], amu0);                              \
                acq0 = ffma2(wv, rCQ[s0], acq0);                              \
                amu1 = ffma2(wv, rMU[s1], amu1);                              \
                acq1 = ffma2(wv, rCQ[s1], acq1);                              \
            }                                                                 \
            po[(POFF)]      = make_float4(amu0.x, amu0.y, acq0.x, acq0.y);    \
            po[(POFF) + WW] = make_float4(amu1.x, amu1.y, acq1.x, acq1.y);    \
        }                                                                     \
    }

    // 9 supersteps (36 steps): mo<3 x (unrolled mm<3). Indices period-3 in m.
    for (int mo = 0; mo < 3; ++mo) {
        #pragma unroll
        for (int mm = 0; mm < 3; ++mm) {
            const int m  = 3 * mo + mm;        // runtime; mm compile-time
            const int k0 = 4 * m;

            // Publish 4 prefetched row-pairs into buffers (4mm..4mm+3)%12.
            #pragma unroll
            for (int i = 0; i < 4; ++i)
                sAB[(4 * mm + i) % 12][x + RAD] = f[i];
            __syncthreads();

            // Fetch superstep m+1's 4 pairs (16 LDGs in flight).
            #pragma unroll
            for (int i = 0; i < 4; ++i)
                f[i] = fetch_pair_p(p1 + 2 * i * WW, p2 + 2 * i * WW,
                                    inRow + 2 * i);

            // Compute the 4 steps; ring bases (8mm+2i)%12 compile-time.
            COMPUTE(k0,     (8 * mm)     % 12, sAB[(4 * mm)     % 12], 0)
            COMPUTE(k0 + 1, (8 * mm + 2) % 12, sAB[(4 * mm + 1) % 12], 2 * WW)
            COMPUTE(k0 + 2, (8 * mm + 4) % 12, sAB[(4 * mm + 2) % 12], 4 * WW)
            COMPUTE(k0 + 3, (8 * mm + 6) % 12, sAB[(4 * mm + 3) % 12], 6 * WW)

            p1 += 8 * WW; p2 += 8 * WW; po += 8 * WW; inRow += 8;
        }
    }

    // Epilogue: step 36 (buffer 36%12 = 0, ring base 72%12 = 0).
    sAB[0][x + RAD] = f[0];
    __syncthreads();
    COMPUTE(36, 0, sAB[0], 0)

    #undef COMPUTE
    #undef W2
}

// ---------------------------------------------------------------------------
// K2: z-conv + SSIM + reduction + finalize. 32-z chunks: 2048 blocks x 128.
// Ring in registers (compile-time slots), depth-4 prefetch, LDG.128 loads.
// (Proven shape: parallelism > halo savings; 64-chunk variants failed twice.)
// ---------------------------------------------------------------------------
__device__ __forceinline__ float4 load_plane(size_t col, int zz) {
    bool ok = (unsigned)zz < DD;
    size_t idx = col + (size_t)(ok ? zz : 0) * SLICE;
    float4 v = g_m4[idx];
    if (!ok) v = make_float4(0.f, 0.f, 0.f, 0.f);
    return v;
}

__global__ __launch_bounds__(128, 5) void conv_z_ssim_kernel(float* __restrict__ out)
{
    const int x  = threadIdx.x;
    const int zc = blockIdx.x;   // z-chunk of 32: 0..3
    const int y  = blockIdx.y;   // 0..127
    const int b  = blockIdx.z;   // 0..3
    const int z0 = zc * 32;
    const size_t col = (size_t)b * VOL + (size_t)y * WW + x;

    float2 w2s[6];
    #pragma unroll
    for (int t = 0; t < 6; ++t) w2s[t] = make_float2(WL[t], WL[t]);
    #define W2(t) w2s[((t) < 6) ? (t) : (10 - (t))]

    // Ring: slot s initially holds relative plane s-5.
    float4 ring[WS];
    #pragma unroll
    for (int s = 0; s < WS; ++s) ring[s] = load_plane(col, z0 + s - RAD);

    // Prefetch pipeline, depth 4: buffers hold relative planes 6..9.
    float4 pf[4];
    #pragma unroll
    for (int q = 0; q < 4; ++q) pf[q] = load_plane(col, z0 + RAD + 1 + q);

    float fsum = 0.f;
    #pragma unroll
    for (int oz = 0; oz < 33; ++oz) {   // 33 = 3*11 so slot math is compile-time
        float2 mu = make_float2(0.f, 0.f), cq = make_float2(0.f, 0.f);
        #pragma unroll
        for (int s = 0; s < WS; ++s) {
            const int wi = ((s - oz) % WS + WS) % WS;   // compile-time
            float2 wv = W2(wi);
            mu = ffma2(wv, make_float2(ring[s].x, ring[s].y), mu);
            cq = ffma2(wv, make_float2(ring[s].z, ring[s].w), cq);
        }
        float2 musq = fmul2(mu, mu);
        float mu12  = mu.x * mu.y;
        float svar  = cq.x - musq.x - musq.y;   // sigma1^2 + sigma2^2
        float s12   = cq.y - mu12;
        float num = (2.f * mu12 + C1F) * (2.f * s12 + C2F);
        float den = (musq.x + musq.y + C1F) * (svar + C2F);
        float v = __fdividef(num, den);
        if (oz < 32) fsum += v;

        // Insert prefetched plane oz+6 (slot oz%11), refill buffer with oz+10.
        ring[oz % WS] = pf[oz & 3];
        pf[oz & 3] = load_plane(col, z0 + oz + RAD + 5);
    }
    #undef W2

    // Block reduction -> global double accumulator -> last block finalizes.
    double dsum = (double)fsum;
    #pragma unroll
    for (int off = 16; off > 0; off >>= 1)
        dsum += __shfl_down_sync(0xffffffffu, dsum, off);

    __shared__ double ssm[4];
    int wid = threadIdx.x >> 5, lid = threadIdx.x & 31;
    if (lid == 0) ssm[wid] = dsum;
    __syncthreads();
    if (threadIdx.x == 0) {
        double tot = ssm[0] + ssm[1] + ssm[2] + ssm[3];
        atomicAdd(&g_acc, tot);
        __threadfence();
        unsigned done = atomicAdd(&g_cnt, 1u);
        if (done == (unsigned)(4 * HH * BATCH - 1)) {   // 2048 blocks
            out[0] = (float)(g_acc * (1.0 / (double)VTOT));
            g_cnt = 0;   // reset for next graph replay
        }
    }
}

// ---------------------------------------------------------------------------
extern "C" void kernel_launch(void* const* d_in, const int* in_sizes, int n_in,
                              void* d_out, int out_size) {
    (void)in_sizes; (void)n_in; (void)out_size;
    const float* img1 = (const float*)d_in[0];
    const float* img2 = (const float*)d_in[1];

    dim3 g1(2, DD, BATCH);                       // (2, 128, 4) = 1024 blocks
    conv_xy_kernel<<<g1, 128>>>(img1, img2);

    dim3 g2(DD / 32, HH, BATCH);                 // (4, 128, 4) = 2048 blocks
    conv_z_ssim_kernel<<<g2, 128>>>((float*)d_out);
}